// round 1
// baseline (speedup 1.0000x reference)
#include <cuda_runtime.h>

// QualityAwarePatchAugment — GB300 sm_103a
// B=32, C=1, H=W=1024, PS=16 -> 64x64 = 4096 patches.
// Two-phase: (A) per-patch stats -> action code/param/m_pp, (B) apply.

#define NPATCH 4096

// Packed per-patch metadata: x=code(as int bits), y=param, z=m_pp
__device__ float4 g_meta[NPATCH];

__device__ __forceinline__ float clipf(float v) {
    return fminf(fmaxf(v, 0.0f), 1.0f);
}

// ---------------------------------------------------------------------------
// Kernel A: per-patch statistics + action code.
// grid = 4096 (one block per patch), block = 256 threads.
// Thread t: batch b = t>>3, sub-lane l8 = t&7. Each thread loads 8 float4s
// (32 pixels) of its batch's patch -> per-thread sum/sumsq -> width-8 shuffle
// reduce -> shared[32] -> warp0 computes per-batch quality and folds batches.
// ---------------------------------------------------------------------------
__global__ void __launch_bounds__(256) stats_kernel(
    const float4* __restrict__ img,
    const float*  __restrict__ r_strong,
    const float*  __restrict__ r_drop,
    const float*  __restrict__ r_else,
    const float*  __restrict__ bright_f,
    const float*  __restrict__ contrast_f,
    const float*  __restrict__ slight_f,
    const int*    __restrict__ aug_choice,
    const int*    __restrict__ slight_choice)
{
    const int p  = blockIdx.x;          // patch linear index, ph*64+pw
    const int ph = p >> 6;
    const int pw = p & 63;
    const int t  = threadIdx.x;
    const int b  = t >> 3;              // batch 0..31
    const int l8 = t & 7;               // 8 threads per batch

    // pixel base of this (batch, patch): (b,  ph*16, pw*16)
    const int pixbase = (b << 20) + ((ph << 4) << 10) + (pw << 4);
    const int f4base  = pixbase >> 2;   // float4 index; row stride = 256 f4

    float s = 0.0f, s2 = 0.0f;
    #pragma unroll
    for (int k = 0; k < 8; k++) {
        const int fi  = l8 + (k << 3);  // float4 slot within patch, 0..63
        const int row = fi >> 2;
        const int c4  = fi & 3;
        const float4 v = img[f4base + (row << 8) + c4];
        s  += v.x + v.y + v.z + v.w;
        s2 += v.x * v.x + v.y * v.y + v.z * v.z + v.w * v.w;
    }
    // width-8 reduce (threads of one batch are 8 consecutive lanes)
    #pragma unroll
    for (int off = 4; off; off >>= 1) {
        s  += __shfl_down_sync(0xffffffffu, s,  off, 8);
        s2 += __shfl_down_sync(0xffffffffu, s2, off, 8);
    }

    __shared__ float sh_s[32], sh_s2[32];
    if (l8 == 0) { sh_s[b] = s; sh_s2[b] = s2; }
    __syncthreads();

    if (t < 32) {
        const float bs  = sh_s[t];
        const float bs2 = sh_s2[t];
        const float mean = bs * (1.0f / 256.0f);
        float var = (bs2 - bs * bs * (1.0f / 256.0f)) * (1.0f / 255.0f); // ddof=1
        var = fmaxf(var, 0.0f);
        const float sd   = sqrtf(var);
        const float iq   = 1.0f - 2.0f * fabsf(mean - 0.5f);
        const float qual = (sd + iq + var) * (1.0f / 3.0f);

        float qs  = qual;   // batch-sum of quality
        float tot = bs;     // batch-sum of pixel sum (for m_pp)
        #pragma unroll
        for (int off = 16; off; off >>= 1) {
            qs  += __shfl_down_sync(0xffffffffu, qs,  off);
            tot += __shfl_down_sync(0xffffffffu, tot, off);
        }
        if (t == 0) {
            const float q   = qs  * (1.0f / 32.0f);
            const float mpp = tot * (1.0f / 8192.0f);   // 32 batches * 256 px

            const bool low    = q < 0.7f;
            const bool strong = low && (r_strong[p] < 0.8f);
            const bool drop   = low && (q < 0.3f) && (r_drop[p] < 0.1f);
            const bool els    = (!low) && (r_else[p] < 0.3f);

            int code = 0;
            if (strong) code = aug_choice[p] + 1;       // 1..4
            if (els)    code = slight_choice[p] + 5;    // 5..6
            if (drop)   code = 7;

            float param = 0.0f;
            switch (code) {
                case 1: param = 0.1f;          break;   // noise scale
                case 3: param = bright_f[p];   break;
                case 4: param = contrast_f[p]; break;
                case 5: param = 0.05f;         break;   // slight noise scale
                case 6: param = slight_f[p];   break;
                default: break;
            }
            g_meta[p] = make_float4(__int_as_float(code), param, mpp, 0.0f);
        }
    }
}

// ---------------------------------------------------------------------------
// Kernel B: apply per-patch action. One thread = one float4 (4 pixels).
// Patch-major thread mapping: t = ((b*64 + ph)*64 + pw)*64 + fq, so every
// warp stays inside ONE patch -> code is warp-uniform (no divergence),
// and noise is only loaded for codes {1,5} (saves ~80% of noise traffic).
// ---------------------------------------------------------------------------
__global__ void __launch_bounds__(256) apply_kernel(
    const float4* __restrict__ img,
    const float4* __restrict__ noise,
    float4*       __restrict__ out)
{
    const int t = blockIdx.x * blockDim.x + threadIdx.x;  // 0 .. 8388607
    const int fq   = t & 63;            // float4 slot within patch
    int rest       = t >> 6;
    const int pw   = rest & 63;
    const int ph   = (rest >> 6) & 63;
    const int b    = rest >> 12;
    const int row  = fq >> 2;
    const int c4   = fq & 3;
    const int y    = (ph << 4) + row;
    const int x0   = (pw << 4) + (c4 << 2);
    const int pix  = (b << 20) + (y << 10) + x0;
    const int fi   = pix >> 2;

    const float4 m = g_meta[(ph << 6) + pw];
    const int code = __float_as_int(m.x);

    float4 o;
    if (code == 0) {                          // identity (~20% of patches)
        o = img[fi];
    } else if (code == 1 || code == 5) {      // noise / slight noise
        const float4 v = img[fi];
        const float4 n = noise[fi];
        const float  s = m.y;
        o.x = clipf(fmaf(s, n.x, v.x));
        o.y = clipf(fmaf(s, n.y, v.y));
        o.z = clipf(fmaf(s, n.z, v.z));
        o.w = clipf(fmaf(s, n.w, v.w));
    } else if (code == 2) {                   // 3x3 avg blur, zero-padded per patch
        float4 acc = make_float4(0.f, 0.f, 0.f, 0.f);
        const float* imgf = (const float*)img;
        #pragma unroll
        for (int dr = -1; dr <= 1; dr++) {
            const int r = row + dr;
            if (r < 0 || r > 15) continue;    // zero padding confined to patch
            const int base = (b << 20) + ((((ph << 4) + r)) << 10) + x0;
            const float4 vv = img[base >> 2];
            const float l  = (c4 > 0) ? __ldg(imgf + base - 1) : 0.0f;
            const float rt = (c4 < 3) ? __ldg(imgf + base + 4) : 0.0f;
            acc.x += l    + vv.x + vv.y;
            acc.y += vv.x + vv.y + vv.z;
            acc.z += vv.y + vv.z + vv.w;
            acc.w += vv.z + vv.w + rt;
        }
        const float inv9 = 1.0f / 9.0f;       // reference does NOT clip blur
        o.x = acc.x * inv9; o.y = acc.y * inv9;
        o.z = acc.z * inv9; o.w = acc.w * inv9;
    } else if (code == 3 || code == 6) {      // brightness / slight brightness
        const float4 v = img[fi];
        const float  f = m.y;
        o.x = clipf(v.x * f); o.y = clipf(v.y * f);
        o.z = clipf(v.z * f); o.w = clipf(v.w * f);
    } else if (code == 4) {                   // contrast about batch-patch mean
        const float4 v  = img[fi];
        const float  cf = m.y;
        const float  mp = m.z;
        o.x = clipf(fmaf(v.x - mp, cf, mp));
        o.y = clipf(fmaf(v.y - mp, cf, mp));
        o.z = clipf(fmaf(v.z - mp, cf, mp));
        o.w = clipf(fmaf(v.w - mp, cf, mp));
    } else {                                  // 7: drop
        o = make_float4(0.f, 0.f, 0.f, 0.f);
    }
    out[fi] = o;
}

extern "C" void kernel_launch(void* const* d_in, const int* in_sizes, int n_in,
                              void* d_out, int out_size)
{
    const float4* img   = (const float4*)d_in[0];
    const float4* noise = (const float4*)d_in[1];

    stats_kernel<<<NPATCH, 256>>>(
        img,
        (const float*)d_in[2],   // r_strong
        (const float*)d_in[3],   // r_drop
        (const float*)d_in[4],   // r_else
        (const float*)d_in[5],   // bright_f
        (const float*)d_in[6],   // contrast_f
        (const float*)d_in[7],   // slight_f
        (const int*)d_in[8],     // aug_choice
        (const int*)d_in[9]);    // slight_choice

    // 32 * 1024 * 1024 / 4 float4s = 8388608 threads
    apply_kernel<<<8388608 / 256, 256>>>(img, noise, (float4*)d_out);
}